// round 15
// baseline (speedup 1.0000x reference)
#include <cuda_runtime.h>
#include <cuda_fp16.h>
#include <cstdint>
#include <climits>

#define NN 100000
#define EE 1600000
#define DD 64
#define ALPHA 0.9f
#define RES_SCALE 0.1f   // (1 - alpha)

// ---------------- helpers ----------------
__device__ __forceinline__ unsigned h2_to_u32(__half2 h) {
    union { __half2 h; unsigned u; } c; c.h = h; return c.u;
}
__device__ __forceinline__ __half2 u32_to_h2(unsigned u) {
    union { unsigned u; __half2 h; } c; c.u = u; return c.h;
}
__device__ __forceinline__ float2 u32_to_f2(unsigned u) {
    return __half22float2(u32_to_h2(u));
}

// ---------------- static device scratch ----------------
// feature buffers have NN+1 rows; row NN is the all-zero pad row
__device__ int4  d_hY [(NN + 1) * 8];   // initial y (half, unscaled): res source
__device__ int4  d_hYs[(NN + 1) * 8];   // dis*y (half): layer-0 input
__device__ int4  d_hB [(NN + 1) * 8];   // buffer B (dis*out)
__device__ int4  d_hC [(NN + 1) * 8];   // buffer C (dis*out)
__device__ int   d_cnt[NN + 1];         // [0,N)=deg, [N]=flagU8 (memset)
__device__ float d_dis[NN];             // deg^{-1/2}
__device__ int   d_off[NN + 1];
__device__ int   d_csr[EE + 3 * NN];    // src*128 byte offsets, padded per node to k*4
__device__ int   d_rank[EE];            // edge rank within its destination
__device__ int   d_agg[128];            // scan aggregates (sentinel INT_MIN)

// ---------------- kernels ----------------
__global__ void k_deg(const int4* __restrict__ col4, const uchar4* __restrict__ m,
                      int E4, int n4) {
    int i = blockIdx.x * blockDim.x + threadIdx.x;
    if (i < 128) d_agg[i] = INT_MIN;
    if (i < E4) {
        int4 c = col4[i];
        int4 r;
        r.x = atomicAdd(&d_cnt[c.x], 1);
        r.y = atomicAdd(&d_cnt[c.y], 1);
        r.z = atomicAdd(&d_cnt[c.z], 1);
        r.w = atomicAdd(&d_cnt[c.w], 1);
        ((int4*)d_rank)[i] = r;
    }
    if (i < n4) {
        uchar4 v = m[i];
        if (v.y | v.z | v.w) d_cnt[NN] = 1;
    }
}

// single-pass exclusive scan (over PADDED degrees) with aggregate lookback.
// Writes off, dis (from real deg), and fills pad slots with zero-row offset.
__global__ void k_scan(int n, int B) {
    __shared__ int sh[1024];
    __shared__ int spref;
    int t = threadIdx.x;
    int b = blockIdx.x;
    int i = b * 1024 + t;

    int v  = (i < n) ? d_cnt[i] : 0;
    int vp = (v + 3) & ~3;                         // padded degree
    if (i < n) d_dis[i] = (v > 0) ? rsqrtf((float)v) : 0.0f;
    sh[t] = vp;
    __syncthreads();
    for (int ofs = 1; ofs < 1024; ofs <<= 1) {
        int x = (t >= ofs) ? sh[t - ofs] : 0;
        __syncthreads();
        sh[t] += x;
        __syncthreads();
    }
    int total = sh[1023];
    if (t == 0) {
        spref = 0;
        atomicExch(&d_agg[b], total);
    }
    __syncthreads();
    if (t < b) {
        int a;
        do { a = atomicAdd(&d_agg[t], 0); } while (a == INT_MIN);
        atomicAdd(&spref, a);
    }
    __syncthreads();
    int pref = spref;

    if (i < n) {
        int off = pref + sh[t] - vp;
        d_off[i] = off;
        const int zoff = NN << 7;                  // zero-row byte offset
        for (int j = v; j < vp; ++j) d_csr[off + j] = zoff;
    }
    if (b == B - 1 && t == 1023) d_off[n] = pref + total;
}

__device__ __forceinline__ int4 pack8(float4 a, float4 b) {
    int4 r;
    r.x = (int)h2_to_u32(__floats2half2_rn(a.x, a.y));
    r.y = (int)h2_to_u32(__floats2half2_rn(a.z, a.w));
    r.z = (int)h2_to_u32(__floats2half2_rn(b.x, b.y));
    r.w = (int)h2_to_u32(__floats2half2_rn(b.z, b.w));
    return r;
}

// fused: scatter (first SB blocks, stores src*128) + init Y/Ys + zero row/count
__global__ void k_build(const int4* __restrict__ row4, const int4* __restrict__ col4, int E4,
                        const void* __restrict__ maskp, const float4* __restrict__ protos,
                        const int* __restrict__ labels, float* __restrict__ cntOut,
                        int n, int SB) {
    if (blockIdx.x < SB) {
        int i = blockIdx.x * blockDim.x + threadIdx.x;
        if (i < E4) {
            int4 c = col4[i];
            int4 r = row4[i];
            int4 k = ((const int4*)d_rank)[i];
            d_csr[__ldg(&d_off[c.x]) + k.x] = r.x << 7;   // src * 128 bytes
            d_csr[__ldg(&d_off[c.y]) + k.y] = r.y << 7;
            d_csr[__ldg(&d_off[c.z]) + k.z] = r.z << 7;
            d_csr[__ldg(&d_off[c.w]) + k.w] = r.w << 7;
        }
    } else {
        int idx = (blockIdx.x - SB) * blockDim.x + threadIdx.x;
        if (idx == 0) cntOut[0] = 0.0f;
        if (idx < 8) {                              // zero pad row in all buffers
            int4 z = make_int4(0, 0, 0, 0);
            d_hYs[n * 8 + idx] = z;
            d_hB [n * 8 + idx] = z;
            d_hC [n * 8 + idx] = z;
        }
        if (idx >= n * 8) return;
        int node = idx >> 3;
        int q    = idx & 7;
        bool tr;
        if (d_cnt[NN]) tr = ((const unsigned char*)maskp)[node] != 0;
        else           tr = ((const int*)maskp)[node] != 0;
        float4 p0 = make_float4(0.f, 0.f, 0.f, 0.f), p1 = p0;
        if (tr) {
            int base = labels[node] * 16 + q * 2;
            p0 = protos[base];
            p1 = protos[base + 1];
        }
        d_hY[idx] = pack8(p0, p1);
        float s = __ldg(&d_dis[node]);
        float4 s0 = make_float4(s * p0.x, s * p0.y, s * p0.z, s * p0.w);
        float4 s1 = make_float4(s * p1.x, s * p1.y, s * p1.z, s * p1.w);
        d_hYs[idx] = pack8(s0, s1);
    }
}

// 8 lanes per node; lane owns 8 features (int4). All inputs dis-premultiplied.
// Segments padded to k*4 edges: one aligned int4 csr load per 4-edge chunk,
// HADD2 tree reduce, single fp32 flush. No remainder paths.
// phase 0: Ys->B, 1: B->C, 2: C->out (+mask/count).
__global__ __launch_bounds__(256, 6) void k_layer(int phase, float4* __restrict__ labelsOut,
                                                  float* __restrict__ maskOut,
                                                  float* __restrict__ cntOut, int n) {
    __shared__ int s_cnt;
    bool last = (phase == 2);
    if (last) {
        if (threadIdx.x == 0) s_cnt = 0;
        __syncthreads();
    }

    int grp  = (blockIdx.x * blockDim.x + threadIdx.x) >> 3;
    int gl   = threadIdx.x & 7;
    int laneInWarp = threadIdx.x & 31;
    bool nonzero = false;

    if (grp < n) {
        const int4* inb = (phase == 0) ? d_hYs : ((phase == 1) ? d_hB : d_hC);
        const char* in = (const char*)inb + (gl << 4);   // lane base folded in

        int start = d_off[grp];
        int end   = d_off[grp + 1];
        float2 acc[4] = {{0.f,0.f},{0.f,0.f},{0.f,0.f},{0.f,0.f}};

        for (int e = start; e < end; e += 4) {
            int4 bb = __ldg((const int4*)(d_csr + e));  // aligned: start % 4 == 0
            int4 v0 = __ldg((const int4*)(in + bb.x));
            int4 v1 = __ldg((const int4*)(in + bb.y));
            __half2 p0 = __hadd2(u32_to_h2((unsigned)v0.x), u32_to_h2((unsigned)v1.x));
            __half2 p1 = __hadd2(u32_to_h2((unsigned)v0.y), u32_to_h2((unsigned)v1.y));
            __half2 p2 = __hadd2(u32_to_h2((unsigned)v0.z), u32_to_h2((unsigned)v1.z));
            __half2 p3 = __hadd2(u32_to_h2((unsigned)v0.w), u32_to_h2((unsigned)v1.w));
            int4 v2 = __ldg((const int4*)(in + bb.z));
            int4 v3 = __ldg((const int4*)(in + bb.w));
            p0 = __hadd2(p0, __hadd2(u32_to_h2((unsigned)v2.x), u32_to_h2((unsigned)v3.x)));
            p1 = __hadd2(p1, __hadd2(u32_to_h2((unsigned)v2.y), u32_to_h2((unsigned)v3.y)));
            p2 = __hadd2(p2, __hadd2(u32_to_h2((unsigned)v2.z), u32_to_h2((unsigned)v3.z)));
            p3 = __hadd2(p3, __hadd2(u32_to_h2((unsigned)v2.w), u32_to_h2((unsigned)v3.w)));
            float2 f;
            f = __half22float2(p0); acc[0].x += f.x; acc[0].y += f.y;
            f = __half22float2(p1); acc[1].x += f.x; acc[1].y += f.y;
            f = __half22float2(p2); acc[2].x += f.x; acc[2].y += f.y;
            f = __half22float2(p3); acc[3].x += f.x; acc[3].y += f.y;
        }

        float disg = __ldg(&d_dis[grp]);
        float sc = ALPHA * disg;

        int4 rv = __ldg(d_hY + grp * 8 + gl);          // res source (unscaled)
        float o[8];
        {
            const unsigned rw[4] = {(unsigned)rv.x, (unsigned)rv.y, (unsigned)rv.z, (unsigned)rv.w};
            #pragma unroll
            for (int k = 0; k < 4; k++) {
                float2 rf = u32_to_f2(rw[k]);
                o[2*k]   = fminf(fmaxf(sc * acc[k].x + RES_SCALE * rf.x, 0.f), 1.f);
                o[2*k+1] = fminf(fmaxf(sc * acc[k].y + RES_SCALE * rf.y, 0.f), 1.f);
            }
        }
        #pragma unroll
        for (int k = 0; k < 8; k++) nonzero |= (o[k] != 0.f);

        if (last) {
            labelsOut[grp * 16 + gl * 2]     = make_float4(o[0], o[1], o[2], o[3]);
            labelsOut[grp * 16 + gl * 2 + 1] = make_float4(o[4], o[5], o[6], o[7]);
        } else {
            int4* outp = (phase == 0) ? d_hB : d_hC;
            int4 w;    // store dis-premultiplied features for next layer
            w.x = (int)h2_to_u32(__floats2half2_rn(disg * o[0], disg * o[1]));
            w.y = (int)h2_to_u32(__floats2half2_rn(disg * o[2], disg * o[3]));
            w.z = (int)h2_to_u32(__floats2half2_rn(disg * o[4], disg * o[5]));
            w.w = (int)h2_to_u32(__floats2half2_rn(disg * o[6], disg * o[7]));
            outp[grp * 8 + gl] = w;
        }
    }

    if (last) {
        unsigned bmask = __ballot_sync(0xffffffffu, nonzero);
        unsigned gbits = (bmask >> (laneInWarp & ~7)) & 0xFFu;
        if (gl == 0 && grp < n) {
            bool notUpd = (gbits == 0u);
            maskOut[grp] = notUpd ? 1.0f : 0.0f;
            if (notUpd) atomicAdd(&s_cnt, 1);
        }
        __syncthreads();
        if (threadIdx.x == 0 && s_cnt) atomicAdd(cntOut, (float)s_cnt);
    }
}

// ---------------- launch ----------------
extern "C" void kernel_launch(void* const* d_in, const int* in_sizes, int n_in,
                              void* d_out, int out_size) {
    const void*  maskp  = d_in[0];                 // bool [N]
    const float* protos = (const float*)d_in[1];   // [C, D] f32
    const int*   labels = (const int*)d_in[2];     // [N] i32
    const int*   edges  = (const int*)d_in[3];     // [2, E] i32

    int N = in_sizes[0];
    int E = in_sizes[3] / 2;
    const int* row = edges;
    const int* col = edges + E;
    int E4 = E / 4;

    float*  out       = (float*)d_out;
    float4* labelsOut = (float4*)out;              // [N*D]
    float*  cntOut    = out + (size_t)N * DD;      // [1]
    float*  maskOut   = cntOut + 1;                // [N]

    void* cntPtr = nullptr;
    cudaGetSymbolAddress(&cntPtr, d_cnt);
    cudaMemsetAsync(cntPtr, 0, (NN + 1) * sizeof(int));   // deg + flag

    k_deg<<<(E4 + 255) / 256, 256>>>((const int4*)col, (const uchar4*)maskp, E4, N / 4);

    int B = (N + 1023) / 1024;                     // 98 blocks, all resident
    k_scan<<<B, 1024>>>(N, B);

    int SB = (E4 + 255) / 256;
    int IB = (N * 8 + 255) / 256;
    k_build<<<SB + IB, 256>>>((const int4*)row, (const int4*)col, E4,
                              maskp, (const float4*)protos, labels, cntOut, N, SB);

    int lb = (N * 8 + 255) / 256;                  // 8 threads per node
    k_layer<<<lb, 256>>>(0, labelsOut, maskOut, cntOut, N);
    k_layer<<<lb, 256>>>(1, labelsOut, maskOut, cntOut, N);
    k_layer<<<lb, 256>>>(2, labelsOut, maskOut, cntOut, N);
}

// round 16
// speedup vs baseline: 1.0580x; 1.0580x over previous
#include <cuda_runtime.h>
#include <cuda_fp16.h>
#include <cstdint>
#include <climits>

#define NN 100000
#define EE 1600000
#define DD 64
#define ALPHA 0.9f
#define RES_SCALE 0.1f   // (1 - alpha)

// ---------------- helpers ----------------
__device__ __forceinline__ unsigned h2_to_u32(__half2 h) {
    union { __half2 h; unsigned u; } c; c.h = h; return c.u;
}
__device__ __forceinline__ __half2 u32_to_h2(unsigned u) {
    union { unsigned u; __half2 h; } c; c.u = u; return c.h;
}
__device__ __forceinline__ float2 u32_to_f2(unsigned u) {
    return __half22float2(u32_to_h2(u));
}

// ---------------- static device scratch ----------------
__device__ int4  d_hY [NN * 8];         // initial y (half, unscaled): res source
__device__ int4  d_hYs[NN * 8];         // dis*y (half): layer-0 input
__device__ int4  d_hB [NN * 8];         // buffer B (dis*out)
__device__ int4  d_hC [NN * 8];         // buffer C (dis*out)
__device__ int   d_cnt[NN];             // degree histogram (self-cleaning in k_scan)
__device__ int   d_flag;                // 1 if mask is u8 (set k_deg, reset k_layer ph2)
__device__ float d_dis[NN];             // deg^{-1/2}
__device__ int   d_off[NN + 1];
__device__ int   d_csr[EE];             // src * 128 (byte offset of node row)
__device__ int   d_rank[EE];            // edge rank within its destination
__device__ int   d_agg[128];            // scan aggregates (sentinel INT_MIN)

// ---------------- kernels ----------------
__global__ void k_deg(const int4* __restrict__ col4, const uchar4* __restrict__ m,
                      int E4, int n4) {
    int i = blockIdx.x * blockDim.x + threadIdx.x;
    if (i < 128) d_agg[i] = INT_MIN;
    if (i < E4) {
        int4 c = col4[i];
        int4 r;
        r.x = atomicAdd(&d_cnt[c.x], 1);
        r.y = atomicAdd(&d_cnt[c.y], 1);
        r.z = atomicAdd(&d_cnt[c.z], 1);
        r.w = atomicAdd(&d_cnt[c.w], 1);
        ((int4*)d_rank)[i] = r;
    }
    if (i < n4) {
        uchar4 v = m[i];
        if (v.y | v.z | v.w) d_flag = 1;
    }
}

// single-pass exclusive scan with aggregate lookback; writes off, dis,
// and ZEROES d_cnt for the next graph replay (self-cleaning).
__global__ void k_scan(int n, int B) {
    __shared__ int sh[1024];
    __shared__ int spref;
    int t = threadIdx.x;
    int b = blockIdx.x;
    int i = b * 1024 + t;

    int v = (i < n) ? d_cnt[i] : 0;
    if (i < n) {
        d_dis[i] = (v > 0) ? rsqrtf((float)v) : 0.0f;
        d_cnt[i] = 0;                              // clean for next replay
    }
    sh[t] = v;
    __syncthreads();
    for (int ofs = 1; ofs < 1024; ofs <<= 1) {
        int x = (t >= ofs) ? sh[t - ofs] : 0;
        __syncthreads();
        sh[t] += x;
        __syncthreads();
    }
    int total = sh[1023];
    if (t == 0) {
        spref = 0;
        atomicExch(&d_agg[b], total);
    }
    __syncthreads();
    if (t < b) {
        int a;
        do { a = atomicAdd(&d_agg[t], 0); } while (a == INT_MIN);
        atomicAdd(&spref, a);
    }
    __syncthreads();
    int pref = spref;

    if (i < n) d_off[i] = pref + sh[t] - v;
    if (b == B - 1 && t == 1023) d_off[n] = pref + total;
}

__device__ __forceinline__ int4 pack8(float4 a, float4 b) {
    int4 r;
    r.x = (int)h2_to_u32(__floats2half2_rn(a.x, a.y));
    r.y = (int)h2_to_u32(__floats2half2_rn(a.z, a.w));
    r.z = (int)h2_to_u32(__floats2half2_rn(b.x, b.y));
    r.w = (int)h2_to_u32(__floats2half2_rn(b.z, b.w));
    return r;
}

// fused: scatter (first SB blocks, stores src*128) + init Y/Ys, zero count
__global__ void k_build(const int4* __restrict__ row4, const int4* __restrict__ col4, int E4,
                        const void* __restrict__ maskp, const float4* __restrict__ protos,
                        const int* __restrict__ labels, float* __restrict__ cntOut,
                        int n, int SB) {
    if (blockIdx.x < SB) {
        int i = blockIdx.x * blockDim.x + threadIdx.x;
        if (i < E4) {
            int4 c = col4[i];
            int4 r = row4[i];
            int4 k = ((const int4*)d_rank)[i];
            d_csr[__ldg(&d_off[c.x]) + k.x] = r.x << 7;   // src * 128 bytes
            d_csr[__ldg(&d_off[c.y]) + k.y] = r.y << 7;
            d_csr[__ldg(&d_off[c.z]) + k.z] = r.z << 7;
            d_csr[__ldg(&d_off[c.w]) + k.w] = r.w << 7;
        }
    } else {
        int idx = (blockIdx.x - SB) * blockDim.x + threadIdx.x;
        if (idx == 0) cntOut[0] = 0.0f;
        if (idx >= n * 8) return;
        int node = idx >> 3;
        int q    = idx & 7;
        bool tr;
        if (d_flag) tr = ((const unsigned char*)maskp)[node] != 0;
        else        tr = ((const int*)maskp)[node] != 0;
        float4 p0 = make_float4(0.f, 0.f, 0.f, 0.f), p1 = p0;
        if (tr) {
            int base = labels[node] * 16 + q * 2;
            p0 = protos[base];
            p1 = protos[base + 1];
        }
        d_hY[idx] = pack8(p0, p1);
        float s = __ldg(&d_dis[node]);
        float4 s0 = make_float4(s * p0.x, s * p0.y, s * p0.z, s * p0.w);
        float4 s1 = make_float4(s * p1.x, s * p1.y, s * p1.z, s * p1.w);
        d_hYs[idx] = pack8(s0, s1);
    }
}

// 8 lanes per node; lane owns 8 features (int4). All inputs dis-premultiplied.
// 4-edge tree reduce: pairs in HADD2, pair-of-pairs in HADD2, one fp32 flush.
// phase 0: Ys->B, 1: B->C, 2: C->out (+mask/count, resets d_flag).
__global__ __launch_bounds__(256, 8) void k_layer(int phase, float4* __restrict__ labelsOut,
                                                  float* __restrict__ maskOut,
                                                  float* __restrict__ cntOut, int n) {
    __shared__ int s_cnt;
    bool last = (phase == 2);
    if (last) {
        if (threadIdx.x == 0) s_cnt = 0;
        __syncthreads();
    }

    int grp  = (blockIdx.x * blockDim.x + threadIdx.x) >> 3;
    int gl   = threadIdx.x & 7;
    int laneInWarp = threadIdx.x & 31;
    bool nonzero = false;

    if (grp < n) {
        const int4* inb = (phase == 0) ? d_hYs : ((phase == 1) ? d_hB : d_hC);
        const char* in = (const char*)inb + (gl << 4);   // lane base folded in

        int start = d_off[grp];
        int end   = d_off[grp + 1];
        float2 acc[4] = {{0.f,0.f},{0.f,0.f},{0.f,0.f},{0.f,0.f}};

        int e = start;
        // 4-edge tree-reduced chunks
        for (; e + 4 <= end; e += 4) {
            int b0 = __ldg(&d_csr[e]);
            int b1 = __ldg(&d_csr[e + 1]);
            int4 v0 = __ldg((const int4*)(in + b0));
            int4 v1 = __ldg((const int4*)(in + b1));
            __half2 p0 = __hadd2(u32_to_h2((unsigned)v0.x), u32_to_h2((unsigned)v1.x));
            __half2 p1 = __hadd2(u32_to_h2((unsigned)v0.y), u32_to_h2((unsigned)v1.y));
            __half2 p2 = __hadd2(u32_to_h2((unsigned)v0.z), u32_to_h2((unsigned)v1.z));
            __half2 p3 = __hadd2(u32_to_h2((unsigned)v0.w), u32_to_h2((unsigned)v1.w));
            int b2 = __ldg(&d_csr[e + 2]);
            int b3 = __ldg(&d_csr[e + 3]);
            int4 v2 = __ldg((const int4*)(in + b2));
            int4 v3 = __ldg((const int4*)(in + b3));
            p0 = __hadd2(p0, __hadd2(u32_to_h2((unsigned)v2.x), u32_to_h2((unsigned)v3.x)));
            p1 = __hadd2(p1, __hadd2(u32_to_h2((unsigned)v2.y), u32_to_h2((unsigned)v3.y)));
            p2 = __hadd2(p2, __hadd2(u32_to_h2((unsigned)v2.z), u32_to_h2((unsigned)v3.z)));
            p3 = __hadd2(p3, __hadd2(u32_to_h2((unsigned)v2.w), u32_to_h2((unsigned)v3.w)));
            float2 f;
            f = __half22float2(p0); acc[0].x += f.x; acc[0].y += f.y;
            f = __half22float2(p1); acc[1].x += f.x; acc[1].y += f.y;
            f = __half22float2(p2); acc[2].x += f.x; acc[2].y += f.y;
            f = __half22float2(p3); acc[3].x += f.x; acc[3].y += f.y;
        }
        // pair remainder
        if (e + 2 <= end) {
            int b0 = __ldg(&d_csr[e]);
            int b1 = __ldg(&d_csr[e + 1]);
            int4 v0 = __ldg((const int4*)(in + b0));
            int4 v1 = __ldg((const int4*)(in + b1));
            e += 2;
            __half2 h; float2 f;
            h = __hadd2(u32_to_h2((unsigned)v0.x), u32_to_h2((unsigned)v1.x));
            f = __half22float2(h); acc[0].x += f.x; acc[0].y += f.y;
            h = __hadd2(u32_to_h2((unsigned)v0.y), u32_to_h2((unsigned)v1.y));
            f = __half22float2(h); acc[1].x += f.x; acc[1].y += f.y;
            h = __hadd2(u32_to_h2((unsigned)v0.z), u32_to_h2((unsigned)v1.z));
            f = __half22float2(h); acc[2].x += f.x; acc[2].y += f.y;
            h = __hadd2(u32_to_h2((unsigned)v0.w), u32_to_h2((unsigned)v1.w));
            f = __half22float2(h); acc[3].x += f.x; acc[3].y += f.y;
        }
        // odd remainder in fp32
        if (e < end) {
            int b0 = __ldg(&d_csr[e]);
            int4 v0 = __ldg((const int4*)(in + b0));
            float2 f;
            f = u32_to_f2((unsigned)v0.x); acc[0].x += f.x; acc[0].y += f.y;
            f = u32_to_f2((unsigned)v0.y); acc[1].x += f.x; acc[1].y += f.y;
            f = u32_to_f2((unsigned)v0.z); acc[2].x += f.x; acc[2].y += f.y;
            f = u32_to_f2((unsigned)v0.w); acc[3].x += f.x; acc[3].y += f.y;
        }

        float disg = __ldg(&d_dis[grp]);
        float sc = ALPHA * disg;

        int4 rv = __ldg(d_hY + grp * 8 + gl);          // res source (unscaled)
        float o[8];
        {
            const unsigned rw[4] = {(unsigned)rv.x, (unsigned)rv.y, (unsigned)rv.z, (unsigned)rv.w};
            #pragma unroll
            for (int k = 0; k < 4; k++) {
                float2 rf = u32_to_f2(rw[k]);
                o[2*k]   = fminf(fmaxf(sc * acc[k].x + RES_SCALE * rf.x, 0.f), 1.f);
                o[2*k+1] = fminf(fmaxf(sc * acc[k].y + RES_SCALE * rf.y, 0.f), 1.f);
            }
        }
        #pragma unroll
        for (int k = 0; k < 8; k++) nonzero |= (o[k] != 0.f);

        if (last) {
            labelsOut[grp * 16 + gl * 2]     = make_float4(o[0], o[1], o[2], o[3]);
            labelsOut[grp * 16 + gl * 2 + 1] = make_float4(o[4], o[5], o[6], o[7]);
        } else {
            int4* outp = (phase == 0) ? d_hB : d_hC;
            int4 w;    // store dis-premultiplied features for next layer
            w.x = (int)h2_to_u32(__floats2half2_rn(disg * o[0], disg * o[1]));
            w.y = (int)h2_to_u32(__floats2half2_rn(disg * o[2], disg * o[3]));
            w.z = (int)h2_to_u32(__floats2half2_rn(disg * o[4], disg * o[5]));
            w.w = (int)h2_to_u32(__floats2half2_rn(disg * o[6], disg * o[7]));
            outp[grp * 8 + gl] = w;
        }
    }

    if (last) {
        unsigned bmask = __ballot_sync(0xffffffffu, nonzero);
        unsigned gbits = (bmask >> (laneInWarp & ~7)) & 0xFFu;
        if (gl == 0 && grp < n) {
            bool notUpd = (gbits == 0u);
            maskOut[grp] = notUpd ? 1.0f : 0.0f;
            if (notUpd) atomicAdd(&s_cnt, 1);
        }
        __syncthreads();
        if (threadIdx.x == 0 && s_cnt) atomicAdd(cntOut, (float)s_cnt);
        if (blockIdx.x == 0 && threadIdx.x == 0) d_flag = 0;   // clean for next replay
    }
}

// ---------------- launch ----------------
extern "C" void kernel_launch(void* const* d_in, const int* in_sizes, int n_in,
                              void* d_out, int out_size) {
    const void*  maskp  = d_in[0];                 // bool [N]
    const float* protos = (const float*)d_in[1];   // [C, D] f32
    const int*   labels = (const int*)d_in[2];     // [N] i32
    const int*   edges  = (const int*)d_in[3];     // [2, E] i32

    int N = in_sizes[0];
    int E = in_sizes[3] / 2;
    const int* row = edges;
    const int* col = edges + E;
    int E4 = E / 4;

    float*  out       = (float*)d_out;
    float4* labelsOut = (float4*)out;              // [N*D]
    float*  cntOut    = out + (size_t)N * DD;      // [1]
    float*  maskOut   = cntOut + 1;                // [N]

    k_deg<<<(E4 + 255) / 256, 256>>>((const int4*)col, (const uchar4*)maskp, E4, N / 4);

    int B = (N + 1023) / 1024;                     // 98 blocks, all resident
    k_scan<<<B, 1024>>>(N, B);

    int SB = (E4 + 255) / 256;
    int IB = (N * 8 + 255) / 256;
    k_build<<<SB + IB, 256>>>((const int4*)row, (const int4*)col, E4,
                              maskp, (const float4*)protos, labels, cntOut, N, SB);

    int lb = (N * 8 + 255) / 256;                  // 8 threads per node
    k_layer<<<lb, 256>>>(0, labelsOut, maskOut, cntOut, N);
    k_layer<<<lb, 256>>>(1, labelsOut, maskOut, cntOut, N);
    k_layer<<<lb, 256>>>(2, labelsOut, maskOut, cntOut, N);
}